// round 13
// baseline (speedup 1.0000x reference)
#include <cuda_runtime.h>
#include <cuda_bf16.h>
#include <cstdint>

#define B_     32
#define NOTES_ 78
#define T_     128
#define NSEQ   2496
#define SPB    24
#define NBLK   104

// ---------------- device scratch ----------------
__device__ uint32_t g_whhA[2 * 8 * 32 * 128];      // Whh A-frag image [hf][kt][mt][lane][q]
__device__ uint32_t g_wxA [2 * 5 * 32 * 128];      // Wih A-frag image
__device__ float    g_xpre[(size_t)T_ * 512 * NSEQ];
__device__ float    g_xpj[(size_t)NSEQ * T_ * 8];

// ---------------- helpers ----------------
__device__ __forceinline__ float sigf(float x)   { return __fdividef(1.f, 1.f + __expf(-x)); }
__device__ __forceinline__ float tanhf_(float x) { return 2.f * sigf(2.f * x) - 1.f; }
__device__ __forceinline__ uint32_t bfhi2(float a, float b) {
    __nv_bfloat162 t = __floats2bfloat162_rn(a, b);
    return *reinterpret_cast<uint32_t*>(&t);
}
__device__ __forceinline__ uint32_t bflo2(float a, float b) {
    __nv_bfloat16 ha = __float2bfloat16_rn(a), hb = __float2bfloat16_rn(b);
    return bfhi2(a - __bfloat162float(ha), b - __bfloat162float(hb));
}
__device__ __forceinline__ void mma_bf16(float* c, const uint32_t* a, uint32_t b0, uint32_t b1) {
    asm volatile("mma.sync.aligned.m16n8k16.row.col.f32.bf16.bf16.f32 "
        "{%0,%1,%2,%3},{%4,%5,%6,%7},{%8,%9},{%0,%1,%2,%3};"
        : "+f"(c[0]), "+f"(c[1]), "+f"(c[2]), "+f"(c[3])
        : "r"(a[0]), "r"(a[1]), "r"(a[2]), "r"(a[3]), "r"(b0), "r"(b1));
}

// ---------------- pack (R10-validated mapping) ----------------
__global__ void pack_kernel(const float* __restrict__ Wih, const float* __restrict__ Whh) {
    int i = blockIdx.x * 256 + threadIdx.x;
    if (i < 65536) {                         // Whh: [hf][kt8][mt32][lane][q]
        int q = i & 3, lane = (i >> 2) & 31, hf = i >> 15;
        int row = ((i >> 7) & 31) * 16 + (lane >> 2) + (q & 1) * 8;
        int k   = ((i >> 12) & 7) * 16 + 2 * (lane & 3) + (q >> 1) * 8;
        float v0 = Whh[row * 128 + k], v1 = Whh[row * 128 + k + 1];
        g_whhA[i] = hf ? bflo2(v0, v1) : bfhi2(v0, v1);
    } else if (i < 106496) {                 // Wih: [hf][kt5][mt][lane][q]
        int j = i - 65536;
        int q = j & 3, lane = (j >> 2) & 31;
        int r = j >> 12, kt = r % 5, hf = r / 5;
        int row = ((j >> 7) & 31) * 16 + (lane >> 2) + (q & 1) * 8;
        int k = kt * 16 + 2 * (lane & 3) + (q >> 1) * 8;
        float v0 = Wih[row * 80 + k], v1 = Wih[row * 80 + k + 1];
        g_wxA[j] = hf ? bflo2(v0, v1) : bfhi2(v0, v1);
    }
}

__global__ void dummy_kernel() {}

// ---------------- xproj (R10 verbatim) ----------------
__global__ __launch_bounds__(512, 1) void xproj_kernel(const float* __restrict__ x) {
    extern __shared__ uint32_t smx[];
    uint32_t* sWx = smx;
    uint32_t* sB  = smx + 40960;
    const int tid = threadIdx.x, w = tid >> 5, lane = tid & 31;
    const int sg0 = (blockIdx.x >> 5) * 64;
    const int tb  = (blockIdx.x & 31) * 4;
    for (int i = tid; i < 40960; i += 512) sWx[i] = g_wxA[i];
    for (int tt = 0; tt < 4; tt++) {
        const int t = tb + tt;
        __syncthreads();
        for (int r = 0; r < 3; r++) {
            int idx = tid + r * 512;
            if (idx < 1280) {
                int s = idx / 20, qq = idx - s * 20, k0 = qq * 4;
                float4 v = *reinterpret_cast<const float4*>(&x[((size_t)(sg0 + s) * T_ + t) * 80 + k0]);
                int kt = k0 >> 4, kk = k0 & 15, nt = s >> 3;
                int lb = (s & 7) * 4 + ((kk & 7) >> 1), reg = kk >> 3;
                uint32_t* ph = &sB[((0 * 5 + kt) * 8 + nt) * 64 + lb * 2 + reg];
                uint32_t* pl = &sB[((1 * 5 + kt) * 8 + nt) * 64 + lb * 2 + reg];
                ph[0] = bfhi2(v.x, v.y); ph[2] = bfhi2(v.z, v.w);
                pl[0] = bflo2(v.x, v.y); pl[2] = bflo2(v.z, v.w);
            }
        }
        __syncthreads();
        float C[2][8][4];
        #pragma unroll
        for (int a = 0; a < 2; a++)
            #pragma unroll
            for (int n = 0; n < 8; n++)
                #pragma unroll
                for (int q = 0; q < 4; q++) C[a][n][q] = 0.f;
        #pragma unroll
        for (int kt = 0; kt < 5; kt++) {
            uint32_t Ah[2][4], Al[2][4];
            #pragma unroll
            for (int mt = 0; mt < 2; mt++) {
                const uint32_t* p  = &sWx[((0 * 5 + kt) * 32 + (2 * w + mt)) * 128 + lane * 4];
                const uint32_t* p2 = &sWx[((1 * 5 + kt) * 32 + (2 * w + mt)) * 128 + lane * 4];
                #pragma unroll
                for (int q = 0; q < 4; q++) { Ah[mt][q] = p[q]; Al[mt][q] = p2[q]; }
            }
            #pragma unroll
            for (int nt = 0; nt < 8; nt++) {
                uint32_t bh0 = sB[((0 * 5 + kt) * 8 + nt) * 64 + lane * 2];
                uint32_t bh1 = sB[((0 * 5 + kt) * 8 + nt) * 64 + lane * 2 + 1];
                uint32_t bl0 = sB[((1 * 5 + kt) * 8 + nt) * 64 + lane * 2];
                uint32_t bl1 = sB[((1 * 5 + kt) * 8 + nt) * 64 + lane * 2 + 1];
                #pragma unroll
                for (int mt = 0; mt < 2; mt++) {
                    mma_bf16(C[mt][nt], Ah[mt], bh0, bh1);
                    mma_bf16(C[mt][nt], Al[mt], bh0, bh1);
                    mma_bf16(C[mt][nt], Ah[mt], bl0, bl1);
                }
            }
        }
        #pragma unroll
        for (int mt = 0; mt < 2; mt++)
            #pragma unroll
            for (int nt = 0; nt < 8; nt++) {
                int row = (2 * w + mt) * 16 + (lane >> 2);
                int sq  = sg0 + nt * 8 + 2 * (lane & 3);
                float* d = &g_xpre[((size_t)t * 512 + row) * NSEQ + sq];
                *reinterpret_cast<float2*>(d) = make_float2(C[mt][nt][0], C[mt][nt][1]);
                *reinterpret_cast<float2*>(d + (size_t)8 * NSEQ) = make_float2(C[mt][nt][2], C[mt][nt][3]);
            }
    }
}

// ---------------- stage 1: seq-group pipelined HMMA LSTM ----------------
// smem: sAhi u32[32768] (128KB) | xq f[512*24] (48KB) | sB16 u16[6144] (12KB)
//       | sh f[2][24*128] (24KB) | sWnT float2[512] (4KB)  = 221184 B
__global__ __launch_bounds__(512, 1) void stage1_kernel(
    const float* __restrict__ bih, const float* __restrict__ bhh,
    const float* __restrict__ Wihn)
{
    extern __shared__ __align__(16) char sm[];
    uint32_t* sAhi = (uint32_t*)sm;
    float*    xq   = (float*)(sm + 131072);
    uint16_t* sB16 = (uint16_t*)(sm + 180224);
    float*    sh   = (float*)(sm + 192512);
    float2*   sWnT = (float2*)(sm + 217088);

    const int tid = threadIdx.x, w = tid >> 5, l = tid & 31;
    const int seq0 = blockIdx.x * SPB;
    const bool ismma = (w < 8);
    const int r1 = (w & 7) * 16 + (l >> 2), r2 = r1 + 8;

    for (int i = tid; i < 32768; i += 512) sAhi[i] = g_whhA[i];
    for (int i = tid; i < 3072; i += 512) ((uint32_t*)sB16)[i] = 0;
    sWnT[tid] = make_float2(Wihn[(tid & 7) * 128 + 2 * (tid >> 3)],
                            Wihn[(tid & 7) * 128 + 2 * (tid >> 3) + 1]);
    {   // stage xq(0)
        const float4* p = (const float4*)&g_xpre[(size_t)tid * NSEQ + seq0];
        float4* q = (float4*)&xq[tid * 24];
        #pragma unroll
        for (int i = 0; i < 6; i++) q[i] = p[i];
    }

    float b4[4][2];
    if (ismma) {
        #pragma unroll
        for (int g = 0; g < 4; g++) {
            b4[g][0] = bih[g * 128 + r1] + bhh[g * 128 + r1];
            b4[g][1] = bih[g * 128 + r2] + bhh[g * 128 + r2];
        }
    }
    float cs[3][4];
    float C[4][3][4];
    #pragma unroll
    for (int nt = 0; nt < 3; nt++)
        #pragma unroll
        for (int q = 0; q < 4; q++) cs[nt][q] = 0.f;

    // act for one (nt, q) pair; shb selects sh buffer
    auto act_pair = [&](int nt_, int q_, int shb) {
        const int rsel = q_ >> 1;
        const int row = rsel ? r2 : r1;
        const int s = nt_ * 8 + 2 * (l & 3) + (q_ & 1);
        float gi = C[0][nt_][q_] + b4[0][rsel];
        float gf = C[1][nt_][q_] + b4[1][rsel];
        float gg = C[2][nt_][q_] + b4[2][rsel];
        float go = C[3][nt_][q_] + b4[3][rsel];
        float cc = sigf(gf) * cs[nt_][q_] + sigf(gi) * tanhf_(gg);
        cs[nt_][q_] = cc;
        float h = sigf(go) * tanhf_(cc);
        sh[shb * 3072 + s * 128 + row] = h;
        __nv_bfloat16 hb = __float2bfloat16_rn(h);
        __nv_bfloat16 lb = __float2bfloat16_rn(h - __bfloat162float(hb));
        const int kt2 = row >> 4, kk = row & 15;
        const int lane2 = (s & 7) * 4 + ((kk & 7) >> 1), reg = kk >> 3, half = kk & 1;
        sB16[(((0 * 8 + kt2) * 3 + nt_) * 32 + lane2) * 4 + reg * 2 + half] =
            *reinterpret_cast<uint16_t*>(&hb);
        sB16[(((1 * 8 + kt2) * 3 + nt_) * 32 + lane2) * 4 + reg * 2 + half] =
            *reinterpret_cast<uint16_t*>(&lb);
    };

    __syncthreads();

    for (int t = 0; t < T_; t++) {
        if (ismma) {
            // ---- C_A init (nt=0) ----
            #pragma unroll
            for (int g = 0; g < 4; g++) {
                int sqb = 2 * (l & 3);
                float2 v  = *(const float2*)&xq[(g * 128 + r1) * 24 + sqb];
                float2 u2 = *(const float2*)&xq[(g * 128 + r2) * 24 + sqb];
                C[g][0][0] = v.x; C[g][0][1] = v.y; C[g][0][2] = u2.x; C[g][0][3] = u2.y;
            }
            // ---- P1: MMA_A(t) interleaved with act_B(t-1) ----
            const uint32_t* pb = (const uint32_t*)sB16;
            uint4 rlo[6];
            #pragma unroll
            for (int u = 0; u < 6; u++)
                rlo[u] = *(const uint4*)&g_whhA[32768 + ((u >> 2) * 32 + (u & 3) * 8 + w) * 128 + l * 4];
            const bool doB = (t > 0);
            const int shbB = (t - 1) & 1;
            #pragma unroll
            for (int kt = 0; kt < 8; kt++) {
                uint2 vh = *(const uint2*)&pb[((0 * 8 + kt) * 3 + 0) * 64 + l * 2];
                uint2 vl = *(const uint2*)&pb[((1 * 8 + kt) * 3 + 0) * 64 + l * 2];
                #pragma unroll
                for (int g = 0; g < 4; g++) {
                    const int u = kt * 4 + g;
                    uint4 ah4 = *(const uint4*)&sAhi[(kt * 32 + g * 8 + w) * 128 + l * 4];
                    uint32_t Ahi[4] = {ah4.x, ah4.y, ah4.z, ah4.w};
                    uint4 alv = rlo[u % 6];
                    if (u < 26) {
                        const int u2 = u + 6;
                        rlo[u % 6] = *(const uint4*)&g_whhA[32768 + ((u2 >> 2) * 32 + (u2 & 3) * 8 + w) * 128 + l * 4];
                    }
                    uint32_t Alo[4] = {alv.x, alv.y, alv.z, alv.w};
                    mma_bf16(C[g][0], Ahi, vh.x, vh.y);
                    mma_bf16(C[g][0], Alo, vh.x, vh.y);
                    mma_bf16(C[g][0], Ahi, vl.x, vl.y);
                }
                if (doB) act_pair(1 + (kt >> 2), kt & 3, shbB);   // 8 pairs of group B
            }
            // ---- C_B init (nt=1,2) — after act_B consumed old C_B ----
            #pragma unroll
            for (int g = 0; g < 4; g++)
                #pragma unroll
                for (int nt = 1; nt < 3; nt++) {
                    int sqb = nt * 8 + 2 * (l & 3);
                    float2 v  = *(const float2*)&xq[(g * 128 + r1) * 24 + sqb];
                    float2 u2 = *(const float2*)&xq[(g * 128 + r2) * 24 + sqb];
                    C[g][nt][0] = v.x; C[g][nt][1] = v.y; C[g][nt][2] = u2.x; C[g][nt][3] = u2.y;
                }
        }
        __syncthreads();   // S1: sBfrag_B(t-1) complete; xq consumed

        if (ismma) {
            // ---- P2: MMA_B(t) interleaved with act_A(t) ----
            const uint32_t* pb = (const uint32_t*)sB16;
            uint4 rlo[6];
            #pragma unroll
            for (int u = 0; u < 6; u++)
                rlo[u] = *(const uint4*)&g_whhA[32768 + ((u >> 2) * 32 + (u & 3) * 8 + w) * 128 + l * 4];
            const int shbA = t & 1;
            #pragma unroll
            for (int kt = 0; kt < 8; kt++) {
                uint32_t bh[2][2], bl[2][2];
                #pragma unroll
                for (int nt = 0; nt < 2; nt++) {
                    uint2 v = *(const uint2*)&pb[((0 * 8 + kt) * 3 + 1 + nt) * 64 + l * 2];
                    bh[nt][0] = v.x; bh[nt][1] = v.y;
                    uint2 v2 = *(const uint2*)&pb[((1 * 8 + kt) * 3 + 1 + nt) * 64 + l * 2];
                    bl[nt][0] = v2.x; bl[nt][1] = v2.y;
                }
                #pragma unroll
                for (int g = 0; g < 4; g++) {
                    const int u = kt * 4 + g;
                    uint4 ah4 = *(const uint4*)&sAhi[(kt * 32 + g * 8 + w) * 128 + l * 4];
                    uint32_t Ahi[4] = {ah4.x, ah4.y, ah4.z, ah4.w};
                    uint4 alv = rlo[u % 6];
                    if (u < 26) {
                        const int u2 = u + 6;
                        rlo[u % 6] = *(const uint4*)&g_whhA[32768 + ((u2 >> 2) * 32 + (u2 & 3) * 8 + w) * 128 + l * 4];
                    }
                    uint32_t Alo[4] = {alv.x, alv.y, alv.z, alv.w};
                    #pragma unroll
                    for (int nt = 0; nt < 2; nt++) {
                        mma_bf16(C[g][1 + nt], Ahi, bh[nt][0], bh[nt][1]);
                        mma_bf16(C[g][1 + nt], Alo, bh[nt][0], bh[nt][1]);
                        mma_bf16(C[g][1 + nt], Ahi, bl[nt][0], bl[nt][1]);
                    }
                }
                if ((kt & 1) == 0) act_pair(0, kt >> 1, shbA);    // 4 pairs of group A
            }
        } else {
            const int at = tid - 256;
            if (t < T_ - 1) {                 // stage xq(t+1)
                #pragma unroll
                for (int rr = 0; rr < 2; rr++) {
                    int row = at * 2 + rr;
                    const float4* p = (const float4*)&g_xpre[((size_t)(t + 1) * 512 + row) * NSEQ + seq0];
                    float4* q = (float4*)&xq[row * 24];
                    #pragma unroll
                    for (int i = 0; i < 6; i++) q[i] = p[i];
                }
            }
            if (t > 0 && at < 192) {          // note-proj(t-1)
                int s = at >> 3, r8 = at & 7;
                const float* hb = &sh[((t - 1) & 1) * 3072 + s * 128];
                const float2* hv = (const float2*)hb;
                float acc = 0.f;
                #pragma unroll
                for (int jj = 0; jj < 64; jj++) {
                    float2 h2 = hv[jj], w2 = sWnT[jj * 8 + r8];
                    acc = fmaf(h2.x, w2.x, fmaf(h2.y, w2.y, acc));
                }
                g_xpj[((size_t)(seq0 + s) * T_ + (t - 1)) * 8 + r8] = acc;
            }
        }
        __syncthreads();   // S2: sBfrag_A(t), sh_A(t), xq(t+1) visible
    }

    if (ismma) {           // act_B(127)
        #pragma unroll
        for (int p = 0; p < 8; p++) act_pair(1 + (p >> 2), p & 3, 1);
    }
    __syncthreads();
    if (tid < 192) {       // note-proj(127)
        int s = tid >> 3, r8 = tid & 7;
        const float2* hv = (const float2*)&sh[3072 + s * 128];
        float acc = 0.f;
        #pragma unroll
        for (int jj = 0; jj < 64; jj++) {
            float2 h2 = hv[jj], w2 = sWnT[jj * 8 + r8];
            acc = fmaf(h2.x, w2.x, fmaf(h2.y, w2.y, acc));
        }
        g_xpj[((size_t)(seq0 + s) * T_ + (T_ - 1)) * 8 + r8] = acc;
    }
}

// ---------------- stage 2: 128 blocks x 32 threads ----------------
__global__ __launch_bounds__(32) void stage2_kernel(
    const float* __restrict__ Whhn,
    const float* __restrict__ bihn, const float* __restrict__ bhhn,
    float* __restrict__ out)
{
    int g = blockIdx.x * 32 + threadIdx.x;
    int b = g >> 7, t = g & 127;
    float W[16];
    #pragma unroll
    for (int i = 0; i < 16; i++) W[i] = Whhn[i];
    float bs[8];
    #pragma unroll
    for (int i = 0; i < 8; i++) bs[i] = bihn[i] + bhhn[i];
    float h0 = 0.f, h1 = 0.f, c0 = 0.f, c1 = 0.f;
    const float4* xp = reinterpret_cast<const float4*>(g_xpj);
    float* op = out + ((size_t)b * T_ + t) * (NOTES_ * 2);
    for (int note = 0; note < NOTES_; note++) {
        size_t base = ((size_t)(b * NOTES_ + note) * T_ + t) * 2;
        float4 xa = xp[base], xb = xp[base + 1];
        float gi0 = xa.x + bs[0] + W[0]  * h0 + W[1]  * h1;
        float gi1 = xa.y + bs[1] + W[2]  * h0 + W[3]  * h1;
        float gf0 = xa.z + bs[2] + W[4]  * h0 + W[5]  * h1;
        float gf1 = xa.w + bs[3] + W[6]  * h0 + W[7]  * h1;
        float gg0 = xb.x + bs[4] + W[8]  * h0 + W[9]  * h1;
        float gg1 = xb.y + bs[5] + W[10] * h0 + W[11] * h1;
        float go0 = xb.z + bs[6] + W[12] * h0 + W[13] * h1;
        float go1 = xb.w + bs[7] + W[14] * h0 + W[15] * h1;
        c0 = sigf(gf0) * c0 + sigf(gi0) * tanhf_(gg0);
        c1 = sigf(gf1) * c1 + sigf(gi1) * tanhf_(gg1);
        h0 = sigf(go0) * tanhf_(c0);
        h1 = sigf(go1) * tanhf_(c1);
        op[note * 2] = h0; op[note * 2 + 1] = h1;
    }
}

// ---------------- launch ----------------
extern "C" void kernel_launch(void* const* d_in, const int* in_sizes, int n_in,
                              void* d_out, int out_size)
{
    const float* x     = (const float*)d_in[0];
    const float* Wih_t = (const float*)d_in[1];
    const float* Whh_t = (const float*)d_in[2];
    const float* bih_t = (const float*)d_in[3];
    const float* bhh_t = (const float*)d_in[4];
    const float* Wih_n = (const float*)d_in[5];
    const float* Whh_n = (const float*)d_in[6];
    const float* bih_n = (const float*)d_in[7];
    const float* bhh_n = (const float*)d_in[8];
    float* out = (float*)d_out;

    const int smx = (40960 + 5120) * 4;   // 184320
    const int sm1 = 221184;
    cudaFuncSetAttribute(xproj_kernel,  cudaFuncAttributeMaxDynamicSharedMemorySize, smx);
    cudaFuncSetAttribute(stage1_kernel, cudaFuncAttributeMaxDynamicSharedMemorySize, sm1);

    // 7 launches; stage1 is global launch #6 so ncu (-s 5 -c 1) profiles it
    pack_kernel<<<(106496 + 255) / 256, 256>>>(Wih_t, Whh_t);
    dummy_kernel<<<1, 32>>>();
    dummy_kernel<<<1, 32>>>();
    dummy_kernel<<<1, 32>>>();
    xproj_kernel<<<39 * 32, 512, smx>>>(x);
    stage1_kernel<<<NBLK, 512, sm1>>>(bih_t, bhh_t, Wih_n);
    stage2_kernel<<<(B_ * T_) / 32, 32>>>(Whh_n, bih_n, bhh_n, out);
}

// round 14
// speedup vs baseline: 1.2778x; 1.2778x over previous
#include <cuda_runtime.h>
#include <cuda_bf16.h>
#include <cstdint>

#define B_     32
#define NOTES_ 78
#define T_     128
#define NSEQ   2496
#define SPB    24
#define NBLK   104

// ---------------- device scratch ----------------
__device__ uint32_t g_whhA[2 * 8 * 32 * 128];      // Whh A-frag image [hf][kt][mt][lane][q]
__device__ uint32_t g_wxA [2 * 5 * 32 * 128];      // Wih A-frag image
__device__ float    g_xpre[(size_t)T_ * 512 * NSEQ];
__device__ float    g_xpj[(size_t)NSEQ * T_ * 8];

// ---------------- helpers ----------------
__device__ __forceinline__ float sigf(float x)   { return __fdividef(1.f, 1.f + __expf(-x)); }
__device__ __forceinline__ float tanhf_(float x) { return 2.f * sigf(2.f * x) - 1.f; }
__device__ __forceinline__ uint32_t bfhi2(float a, float b) {
    __nv_bfloat162 t = __floats2bfloat162_rn(a, b);
    return *reinterpret_cast<uint32_t*>(&t);
}
__device__ __forceinline__ uint32_t bflo2(float a, float b) {
    __nv_bfloat16 ha = __float2bfloat16_rn(a), hb = __float2bfloat16_rn(b);
    return bfhi2(a - __bfloat162float(ha), b - __bfloat162float(hb));
}
__device__ __forceinline__ void mma_bf16(float* c, const uint32_t* a, uint32_t b0, uint32_t b1) {
    asm volatile("mma.sync.aligned.m16n8k16.row.col.f32.bf16.bf16.f32 "
        "{%0,%1,%2,%3},{%4,%5,%6,%7},{%8,%9},{%0,%1,%2,%3};"
        : "+f"(c[0]), "+f"(c[1]), "+f"(c[2]), "+f"(c[3])
        : "r"(a[0]), "r"(a[1]), "r"(a[2]), "r"(a[3]), "r"(b0), "r"(b1));
}

// ---------------- pack (R10-validated mapping) ----------------
__global__ void pack_kernel(const float* __restrict__ Wih, const float* __restrict__ Whh) {
    int i = blockIdx.x * 256 + threadIdx.x;
    if (i < 65536) {                         // Whh: [hf][kt8][mt32][lane][q]
        int q = i & 3, lane = (i >> 2) & 31, hf = i >> 15;
        int row = ((i >> 7) & 31) * 16 + (lane >> 2) + (q & 1) * 8;
        int k   = ((i >> 12) & 7) * 16 + 2 * (lane & 3) + (q >> 1) * 8;
        float v0 = Whh[row * 128 + k], v1 = Whh[row * 128 + k + 1];
        g_whhA[i] = hf ? bflo2(v0, v1) : bfhi2(v0, v1);
    } else if (i < 106496) {                 // Wih: [hf][kt5][mt][lane][q]
        int j = i - 65536;
        int q = j & 3, lane = (j >> 2) & 31;
        int r = j >> 12, kt = r % 5, hf = r / 5;
        int row = ((j >> 7) & 31) * 16 + (lane >> 2) + (q & 1) * 8;
        int k = kt * 16 + 2 * (lane & 3) + (q >> 1) * 8;
        float v0 = Wih[row * 80 + k], v1 = Wih[row * 80 + k + 1];
        g_wxA[j] = hf ? bflo2(v0, v1) : bfhi2(v0, v1);
    }
}

// ---------------- xproj (R10 verbatim) ----------------
__global__ __launch_bounds__(512, 1) void xproj_kernel(const float* __restrict__ x) {
    extern __shared__ uint32_t smx[];
    uint32_t* sWx = smx;
    uint32_t* sB  = smx + 40960;
    const int tid = threadIdx.x, w = tid >> 5, lane = tid & 31;
    const int sg0 = (blockIdx.x >> 5) * 64;
    const int tb  = (blockIdx.x & 31) * 4;
    for (int i = tid; i < 40960; i += 512) sWx[i] = g_wxA[i];
    for (int tt = 0; tt < 4; tt++) {
        const int t = tb + tt;
        __syncthreads();
        for (int r = 0; r < 3; r++) {
            int idx = tid + r * 512;
            if (idx < 1280) {
                int s = idx / 20, qq = idx - s * 20, k0 = qq * 4;
                float4 v = *reinterpret_cast<const float4*>(&x[((size_t)(sg0 + s) * T_ + t) * 80 + k0]);
                int kt = k0 >> 4, kk = k0 & 15, nt = s >> 3;
                int lb = (s & 7) * 4 + ((kk & 7) >> 1), reg = kk >> 3;
                uint32_t* ph = &sB[((0 * 5 + kt) * 8 + nt) * 64 + lb * 2 + reg];
                uint32_t* pl = &sB[((1 * 5 + kt) * 8 + nt) * 64 + lb * 2 + reg];
                ph[0] = bfhi2(v.x, v.y); ph[2] = bfhi2(v.z, v.w);
                pl[0] = bflo2(v.x, v.y); pl[2] = bflo2(v.z, v.w);
            }
        }
        __syncthreads();
        float C[2][8][4];
        #pragma unroll
        for (int a = 0; a < 2; a++)
            #pragma unroll
            for (int n = 0; n < 8; n++)
                #pragma unroll
                for (int q = 0; q < 4; q++) C[a][n][q] = 0.f;
        #pragma unroll
        for (int kt = 0; kt < 5; kt++) {
            uint32_t Ah[2][4], Al[2][4];
            #pragma unroll
            for (int mt = 0; mt < 2; mt++) {
                const uint32_t* p  = &sWx[((0 * 5 + kt) * 32 + (2 * w + mt)) * 128 + lane * 4];
                const uint32_t* p2 = &sWx[((1 * 5 + kt) * 32 + (2 * w + mt)) * 128 + lane * 4];
                #pragma unroll
                for (int q = 0; q < 4; q++) { Ah[mt][q] = p[q]; Al[mt][q] = p2[q]; }
            }
            #pragma unroll
            for (int nt = 0; nt < 8; nt++) {
                uint32_t bh0 = sB[((0 * 5 + kt) * 8 + nt) * 64 + lane * 2];
                uint32_t bh1 = sB[((0 * 5 + kt) * 8 + nt) * 64 + lane * 2 + 1];
                uint32_t bl0 = sB[((1 * 5 + kt) * 8 + nt) * 64 + lane * 2];
                uint32_t bl1 = sB[((1 * 5 + kt) * 8 + nt) * 64 + lane * 2 + 1];
                #pragma unroll
                for (int mt = 0; mt < 2; mt++) {
                    mma_bf16(C[mt][nt], Ah[mt], bh0, bh1);
                    mma_bf16(C[mt][nt], Al[mt], bh0, bh1);
                    mma_bf16(C[mt][nt], Ah[mt], bl0, bl1);
                }
            }
        }
        #pragma unroll
        for (int mt = 0; mt < 2; mt++)
            #pragma unroll
            for (int nt = 0; nt < 8; nt++) {
                int row = (2 * w + mt) * 16 + (lane >> 2);
                int sq  = sg0 + nt * 8 + 2 * (lane & 3);
                float* d = &g_xpre[((size_t)t * 512 + row) * NSEQ + sq];
                *reinterpret_cast<float2*>(d) = make_float2(C[mt][nt][0], C[mt][nt][1]);
                *reinterpret_cast<float2*>(d + (size_t)8 * NSEQ) = make_float2(C[mt][nt][2], C[mt][nt][3]);
            }
    }
}

// ---------------- stage 1: K-split 16-warp HMMA LSTM ----------------
// smem: sAhi u32[32768] 128KB | sCx f[12288] 48KB | sB16 u16[6144] 12KB
//       | sh f[2][3072] 24KB | sWnT float2[512] 4KB   = 221184 B
__global__ __launch_bounds__(512, 1) void stage1_kernel(
    const float* __restrict__ bih, const float* __restrict__ bhh,
    const float* __restrict__ Wihn)
{
    extern __shared__ __align__(16) char sm[];
    uint32_t* sAhi = (uint32_t*)sm;
    float*    sCx  = (float*)(sm + 131072);
    uint16_t* sB16 = (uint16_t*)(sm + 180224);
    float*    sh   = (float*)(sm + 192512);
    float2*   sWnT = (float2*)(sm + 217088);

    const int tid = threadIdx.x, w = tid >> 5, l = tid & 31;
    const int rb = w & 7;            // row block
    const int hk = w >> 3;           // 0 = primary (K 0..63), 1 = partner (K 64..127)
    const int seq0 = blockIdx.x * SPB;
    const int r1 = rb * 16 + (l >> 2), r2 = r1 + 8;

    for (int i = tid; i < 32768; i += 512) sAhi[i] = g_whhA[i];
    for (int i = tid; i < 3072; i += 512) ((uint32_t*)sB16)[i] = 0;
    sWnT[tid] = make_float2(Wihn[(tid & 7) * 128 + 2 * (tid >> 3)],
                            Wihn[(tid & 7) * 128 + 2 * (tid >> 3) + 1]);

    float b4[4][2];
    float cs[3][4];
    float C[4][3][4];
    if (hk == 0) {
        #pragma unroll
        for (int g = 0; g < 4; g++) {
            b4[g][0] = bih[g * 128 + r1] + bhh[g * 128 + r1];
            b4[g][1] = bih[g * 128 + r2] + bhh[g * 128 + r2];
        }
        #pragma unroll
        for (int nt = 0; nt < 3; nt++)
            #pragma unroll
            for (int q = 0; q < 4; q++) cs[nt][q] = 0.f;
        // preload xpre(0) straight into C
        #pragma unroll
        for (int g = 0; g < 4; g++)
            #pragma unroll
            for (int nt = 0; nt < 3; nt++) {
                const int sq = seq0 + nt * 8 + 2 * (l & 3);
                float2 v  = *(const float2*)&g_xpre[((size_t)(g * 128 + r1)) * NSEQ + sq];
                float2 u2 = *(const float2*)&g_xpre[((size_t)(g * 128 + r2)) * NSEQ + sq];
                C[g][nt][0] = v.x; C[g][nt][1] = v.y; C[g][nt][2] = u2.x; C[g][nt][3] = u2.y;
            }
    }
    __syncthreads();

    for (int t = 0; t < T_; t++) {
        if (hk) {   // partner accumulates from zero
            #pragma unroll
            for (int g = 0; g < 4; g++)
                #pragma unroll
                for (int nt = 0; nt < 3; nt++)
                    #pragma unroll
                    for (int q = 0; q < 4; q++) C[g][nt][q] = 0.f;
        }
        // ---- MMA over this warp's K half ----
        {
            const uint32_t* pb = (const uint32_t*)sB16;
            uint4 rlo[4];
            #pragma unroll
            for (int u = 0; u < 4; u++) {
                const int ut = hk * 16 + u;
                rlo[u] = *(const uint4*)&g_whhA[32768 + ((ut >> 2) * 32 + (ut & 3) * 8 + rb) * 128 + l * 4];
            }
            #pragma unroll
            for (int kl = 0; kl < 4; kl++) {
                const int kt = hk * 4 + kl;
                uint2 bh[3], bl[3];
                #pragma unroll
                for (int nt = 0; nt < 3; nt++) {
                    bh[nt] = *(const uint2*)&pb[((0 * 8 + kt) * 3 + nt) * 64 + l * 2];
                    bl[nt] = *(const uint2*)&pb[((1 * 8 + kt) * 3 + nt) * 64 + l * 2];
                }
                #pragma unroll
                for (int g = 0; g < 4; g++) {
                    const int ul = kl * 4 + g;
                    uint4 a4 = *(const uint4*)&sAhi[(kt * 32 + g * 8 + rb) * 128 + l * 4];
                    uint32_t Ahi[4] = {a4.x, a4.y, a4.z, a4.w};
                    uint4 alv = rlo[ul & 3];
                    if (ul < 12) {
                        const int un = hk * 16 + ul + 4;
                        rlo[ul & 3] = *(const uint4*)&g_whhA[32768 + ((un >> 2) * 32 + (un & 3) * 8 + rb) * 128 + l * 4];
                    }
                    uint32_t Alo[4] = {alv.x, alv.y, alv.z, alv.w};
                    #pragma unroll
                    for (int nt = 0; nt < 3; nt++) {
                        mma_bf16(C[g][nt], Ahi, bh[nt].x, bh[nt].y);
                        mma_bf16(C[g][nt], Alo, bh[nt].x, bh[nt].y);
                        mma_bf16(C[g][nt], Ahi, bl[nt].x, bl[nt].y);
                    }
                }
            }
        }
        if (hk) {   // partner: publish partial C
            #pragma unroll
            for (int nt = 0; nt < 3; nt++)
                #pragma unroll
                for (int g = 0; g < 4; g++)
                    *(float4*)&sCx[(((nt * 4 + g) * 8 + rb) * 32 + l) * 4] =
                        make_float4(C[g][nt][0], C[g][nt][1], C[g][nt][2], C[g][nt][3]);
        }
        __syncthreads();    // S1: B(t-1) reads done; partials visible

        if (hk == 0) {
            // sum partials
            #pragma unroll
            for (int nt = 0; nt < 3; nt++)
                #pragma unroll
                for (int g = 0; g < 4; g++) {
                    float4 v = *(const float4*)&sCx[(((nt * 4 + g) * 8 + rb) * 32 + l) * 4];
                    C[g][nt][0] += v.x; C[g][nt][1] += v.y; C[g][nt][2] += v.z; C[g][nt][3] += v.w;
                }
            // act: 12 (cell, seq) pairs, writes sh(t) + B(t) frags
            #pragma unroll
            for (int nt = 0; nt < 3; nt++)
                #pragma unroll
                for (int q = 0; q < 4; q++) {
                    const int rsel = q >> 1;
                    const int row = rsel ? r2 : r1;
                    const int s = nt * 8 + 2 * (l & 3) + (q & 1);
                    float gi = C[0][nt][q] + b4[0][rsel];
                    float gf = C[1][nt][q] + b4[1][rsel];
                    float gg = C[2][nt][q] + b4[2][rsel];
                    float go = C[3][nt][q] + b4[3][rsel];
                    float cc = sigf(gf) * cs[nt][q] + sigf(gi) * tanhf_(gg);
                    cs[nt][q] = cc;
                    float h = sigf(go) * tanhf_(cc);
                    sh[(t & 1) * 3072 + s * 128 + row] = h;
                    __nv_bfloat16 hb = __float2bfloat16_rn(h);
                    __nv_bfloat16 lb = __float2bfloat16_rn(h - __bfloat162float(hb));
                    const int kt2 = row >> 4, kk = row & 15;
                    const int lane2 = (s & 7) * 4 + ((kk & 7) >> 1), reg = kk >> 3, hf2 = kk & 1;
                    sB16[(((0 * 8 + kt2) * 3 + nt) * 32 + lane2) * 4 + reg * 2 + hf2] =
                        *reinterpret_cast<uint16_t*>(&hb);
                    sB16[(((1 * 8 + kt2) * 3 + nt) * 32 + lane2) * 4 + reg * 2 + hf2] =
                        *reinterpret_cast<uint16_t*>(&lb);
                }
            // prefetch xpre(t+1) straight into the now-dead C regs
            if (t < T_ - 1) {
                #pragma unroll
                for (int g = 0; g < 4; g++)
                    #pragma unroll
                    for (int nt = 0; nt < 3; nt++) {
                        const int sq = seq0 + nt * 8 + 2 * (l & 3);
                        float2 v  = *(const float2*)&g_xpre[((size_t)(t + 1) * 512 + g * 128 + r1) * NSEQ + sq];
                        float2 u2 = *(const float2*)&g_xpre[((size_t)(t + 1) * 512 + g * 128 + r2) * NSEQ + sq];
                        C[g][nt][0] = v.x; C[g][nt][1] = v.y; C[g][nt][2] = u2.x; C[g][nt][3] = u2.y;
                    }
            }
        } else {
            // partner: note-projection for t-1
            const int at = tid - 256;
            if (t > 0 && at < 192) {
                const int s = at >> 3, r8 = at & 7;
                const float2* hv = (const float2*)&sh[((t - 1) & 1) * 3072 + s * 128];
                float acc = 0.f;
                #pragma unroll
                for (int jj = 0; jj < 64; jj++) {
                    float2 h2 = hv[jj], w2 = sWnT[jj * 8 + r8];
                    acc = fmaf(h2.x, w2.x, fmaf(h2.y, w2.y, acc));
                }
                g_xpj[((size_t)(seq0 + s) * T_ + (t - 1)) * 8 + r8] = acc;
            }
        }
        __syncthreads();    // S2: B(t), sh(t) complete
    }

    if (tid < 192) {        // note-projection for t = 127
        const int s = tid >> 3, r8 = tid & 7;
        const float2* hv = (const float2*)&sh[((T_ - 1) & 1) * 3072 + s * 128];
        float acc = 0.f;
        #pragma unroll
        for (int jj = 0; jj < 64; jj++) {
            float2 h2 = hv[jj], w2 = sWnT[jj * 8 + r8];
            acc = fmaf(h2.x, w2.x, fmaf(h2.y, w2.y, acc));
        }
        g_xpj[((size_t)(seq0 + s) * T_ + (T_ - 1)) * 8 + r8] = acc;
    }
}

// ---------------- stage 2: 128 blocks x 32 threads ----------------
__global__ __launch_bounds__(32) void stage2_kernel(
    const float* __restrict__ Whhn,
    const float* __restrict__ bihn, const float* __restrict__ bhhn,
    float* __restrict__ out)
{
    int g = blockIdx.x * 32 + threadIdx.x;
    int b = g >> 7, t = g & 127;
    float W[16];
    #pragma unroll
    for (int i = 0; i < 16; i++) W[i] = Whhn[i];
    float bs[8];
    #pragma unroll
    for (int i = 0; i < 8; i++) bs[i] = bihn[i] + bhhn[i];
    float h0 = 0.f, h1 = 0.f, c0 = 0.f, c1 = 0.f;
    const float4* xp = reinterpret_cast<const float4*>(g_xpj);
    float* op = out + ((size_t)b * T_ + t) * (NOTES_ * 2);
    for (int note = 0; note < NOTES_; note++) {
        size_t base = ((size_t)(b * NOTES_ + note) * T_ + t) * 2;
        float4 xa = xp[base], xb = xp[base + 1];
        float gi0 = xa.x + bs[0] + W[0]  * h0 + W[1]  * h1;
        float gi1 = xa.y + bs[1] + W[2]  * h0 + W[3]  * h1;
        float gf0 = xa.z + bs[2] + W[4]  * h0 + W[5]  * h1;
        float gf1 = xa.w + bs[3] + W[6]  * h0 + W[7]  * h1;
        float gg0 = xb.x + bs[4] + W[8]  * h0 + W[9]  * h1;
        float gg1 = xb.y + bs[5] + W[10] * h0 + W[11] * h1;
        float go0 = xb.z + bs[6] + W[12] * h0 + W[13] * h1;
        float go1 = xb.w + bs[7] + W[14] * h0 + W[15] * h1;
        c0 = sigf(gf0) * c0 + sigf(gi0) * tanhf_(gg0);
        c1 = sigf(gf1) * c1 + sigf(gi1) * tanhf_(gg1);
        h0 = sigf(go0) * tanhf_(c0);
        h1 = sigf(go1) * tanhf_(c1);
        op[note * 2] = h0; op[note * 2 + 1] = h1;
    }
}

// ---------------- launch ----------------
extern "C" void kernel_launch(void* const* d_in, const int* in_sizes, int n_in,
                              void* d_out, int out_size)
{
    const float* x     = (const float*)d_in[0];
    const float* Wih_t = (const float*)d_in[1];
    const float* Whh_t = (const float*)d_in[2];
    const float* bih_t = (const float*)d_in[3];
    const float* bhh_t = (const float*)d_in[4];
    const float* Wih_n = (const float*)d_in[5];
    const float* Whh_n = (const float*)d_in[6];
    const float* bih_n = (const float*)d_in[7];
    const float* bhh_n = (const float*)d_in[8];
    float* out = (float*)d_out;

    const int smx = (40960 + 5120) * 4;   // 184320
    const int sm1 = 221184;
    cudaFuncSetAttribute(xproj_kernel,  cudaFuncAttributeMaxDynamicSharedMemorySize, smx);
    cudaFuncSetAttribute(stage1_kernel, cudaFuncAttributeMaxDynamicSharedMemorySize, sm1);

    pack_kernel<<<(106496 + 255) / 256, 256>>>(Wih_t, Whh_t);
    xproj_kernel<<<39 * 32, 512, smx>>>(x);
    stage1_kernel<<<NBLK, 512, sm1>>>(bih_t, bhh_t, Wih_n);
    stage2_kernel<<<(B_ * T_) / 32, 32>>>(Whh_n, bih_n, bhh_n, out);
}

// round 15
// speedup vs baseline: 1.3789x; 1.0791x over previous
#include <cuda_runtime.h>
#include <cuda_bf16.h>
#include <cuda_fp16.h>
#include <cstdint>

#define B_     32
#define NOTES_ 78
#define T_     128
#define NSEQ   2496
#define SPB    24
#define NBLK   104

// ---------------- device scratch ----------------
// hf0 slot: f16(W) pairs; hf1 slot: bf16(W - f16(W)) pairs
__device__ uint32_t g_whhA[2 * 8 * 32 * 128];
__device__ uint32_t g_wxA [2 * 5 * 32 * 128];
__device__ float    g_xpre[(size_t)T_ * 512 * NSEQ];
__device__ float    g_xpj[(size_t)NSEQ * T_ * 8];

// ---------------- helpers ----------------
__device__ __forceinline__ float sigf(float x)   { return __fdividef(1.f, 1.f + __expf(-x)); }
__device__ __forceinline__ float tanhf_(float x) { return 2.f * sigf(2.f * x) - 1.f; }
__device__ __forceinline__ uint32_t bf2(float a, float b) {          // bf16 pair (full value)
    __nv_bfloat162 t = __floats2bfloat162_rn(a, b);
    return *reinterpret_cast<uint32_t*>(&t);
}
__device__ __forceinline__ uint32_t h2(float a, float b) {           // f16 pair
    __half2 t = __floats2half2_rn(a, b);
    return *reinterpret_cast<uint32_t*>(&t);
}
__device__ __forceinline__ uint32_t resbf2(float a, float b) {       // bf16 of (v - f16(v))
    __half2 t = __floats2half2_rn(a, b);
    float ra = a - __half2float(__low2half(t));
    float rb = b - __half2float(__high2half(t));
    return bf2(ra, rb);
}
__device__ __forceinline__ void mma_bf16(float* c, const uint32_t* a, uint32_t b0, uint32_t b1) {
    asm volatile("mma.sync.aligned.m16n8k16.row.col.f32.bf16.bf16.f32 "
        "{%0,%1,%2,%3},{%4,%5,%6,%7},{%8,%9},{%0,%1,%2,%3};"
        : "+f"(c[0]), "+f"(c[1]), "+f"(c[2]), "+f"(c[3])
        : "r"(a[0]), "r"(a[1]), "r"(a[2]), "r"(a[3]), "r"(b0), "r"(b1));
}
__device__ __forceinline__ void mma_f16(float* c, const uint32_t* a, uint32_t b0, uint32_t b1) {
    asm volatile("mma.sync.aligned.m16n8k16.row.col.f32.f16.f16.f32 "
        "{%0,%1,%2,%3},{%4,%5,%6,%7},{%8,%9},{%0,%1,%2,%3};"
        : "+f"(c[0]), "+f"(c[1]), "+f"(c[2]), "+f"(c[3])
        : "r"(a[0]), "r"(a[1]), "r"(a[2]), "r"(a[3]), "r"(b0), "r"(b1));
}

// ---------------- pack (same index mapping as R10/R14) ----------------
__global__ void pack_kernel(const float* __restrict__ Wih, const float* __restrict__ Whh) {
    int i = blockIdx.x * 256 + threadIdx.x;
    if (i < 65536) {                         // Whh: [hf][kt8][mt32][lane][q]
        int q = i & 3, lane = (i >> 2) & 31, hf = i >> 15;
        int row = ((i >> 7) & 31) * 16 + (lane >> 2) + (q & 1) * 8;
        int k   = ((i >> 12) & 7) * 16 + 2 * (lane & 3) + (q >> 1) * 8;
        float v0 = Whh[row * 128 + k], v1 = Whh[row * 128 + k + 1];
        g_whhA[i] = hf ? resbf2(v0, v1) : h2(v0, v1);
    } else if (i < 106496) {                 // Wih: [hf][kt5][mt][lane][q]
        int j = i - 65536;
        int q = j & 3, lane = (j >> 2) & 31;
        int r = j >> 12, kt = r % 5, hf = r / 5;
        int row = ((j >> 7) & 31) * 16 + (lane >> 2) + (q & 1) * 8;
        int k = kt * 16 + 2 * (lane & 3) + (q >> 1) * 8;
        float v0 = Wih[row * 80 + k], v1 = Wih[row * 80 + k + 1];
        g_wxA[j] = hf ? resbf2(v0, v1) : h2(v0, v1);
    }
}

// ---------------- xproj: 2-term mixed f16/bf16 ----------------
__global__ __launch_bounds__(512, 1) void xproj_kernel(const float* __restrict__ x) {
    extern __shared__ uint32_t smx[];
    uint32_t* sWx = smx;
    uint32_t* sB  = smx + 40960;
    const int tid = threadIdx.x, w = tid >> 5, lane = tid & 31;
    const int sg0 = (blockIdx.x >> 5) * 64;
    const int tb  = (blockIdx.x & 31) * 4;
    for (int i = tid; i < 40960; i += 512) sWx[i] = g_wxA[i];
    for (int tt = 0; tt < 4; tt++) {
        const int t = tb + tt;
        __syncthreads();
        for (int r = 0; r < 3; r++) {
            int idx = tid + r * 512;
            if (idx < 1280) {
                int s = idx / 20, qq = idx - s * 20, k0 = qq * 4;
                float4 v = *reinterpret_cast<const float4*>(&x[((size_t)(sg0 + s) * T_ + t) * 80 + k0]);
                int kt = k0 >> 4, kk = k0 & 15, nt = s >> 3;
                int lb = (s & 7) * 4 + ((kk & 7) >> 1), reg = kk >> 3;
                uint32_t* ph = &sB[((0 * 5 + kt) * 8 + nt) * 64 + lb * 2 + reg];   // f16 copy
                uint32_t* pl = &sB[((1 * 5 + kt) * 8 + nt) * 64 + lb * 2 + reg];   // bf16 copy
                ph[0] = h2(v.x, v.y);  ph[2] = h2(v.z, v.w);
                pl[0] = bf2(v.x, v.y); pl[2] = bf2(v.z, v.w);
            }
        }
        __syncthreads();
        float C[2][8][4];
        #pragma unroll
        for (int a = 0; a < 2; a++)
            #pragma unroll
            for (int n = 0; n < 8; n++)
                #pragma unroll
                for (int q = 0; q < 4; q++) C[a][n][q] = 0.f;
        #pragma unroll
        for (int kt = 0; kt < 5; kt++) {
            uint32_t Ah[2][4], Al[2][4];
            #pragma unroll
            for (int mt = 0; mt < 2; mt++) {
                const uint32_t* p  = &sWx[((0 * 5 + kt) * 32 + (2 * w + mt)) * 128 + lane * 4];
                const uint32_t* p2 = &sWx[((1 * 5 + kt) * 32 + (2 * w + mt)) * 128 + lane * 4];
                #pragma unroll
                for (int q = 0; q < 4; q++) { Ah[mt][q] = p[q]; Al[mt][q] = p2[q]; }
            }
            #pragma unroll
            for (int nt = 0; nt < 8; nt++) {
                uint32_t bh0 = sB[((0 * 5 + kt) * 8 + nt) * 64 + lane * 2];
                uint32_t bh1 = sB[((0 * 5 + kt) * 8 + nt) * 64 + lane * 2 + 1];
                uint32_t bl0 = sB[((1 * 5 + kt) * 8 + nt) * 64 + lane * 2];
                uint32_t bl1 = sB[((1 * 5 + kt) * 8 + nt) * 64 + lane * 2 + 1];
                #pragma unroll
                for (int mt = 0; mt < 2; mt++) {
                    mma_f16 (C[mt][nt], Ah[mt], bh0, bh1);
                    mma_bf16(C[mt][nt], Al[mt], bl0, bl1);
                }
            }
        }
        #pragma unroll
        for (int mt = 0; mt < 2; mt++)
            #pragma unroll
            for (int nt = 0; nt < 8; nt++) {
                int row = (2 * w + mt) * 16 + (lane >> 2);
                int sq  = sg0 + nt * 8 + 2 * (lane & 3);
                float* d = &g_xpre[((size_t)t * 512 + row) * NSEQ + sq];
                *reinterpret_cast<float2*>(d) = make_float2(C[mt][nt][0], C[mt][nt][1]);
                *reinterpret_cast<float2*>(d + (size_t)8 * NSEQ) = make_float2(C[mt][nt][2], C[mt][nt][3]);
            }
    }
}

// ---------------- stage 1: K-split 16-warp, 2-term mixed MMA ----------------
__global__ __launch_bounds__(512, 1) void stage1_kernel(
    const float* __restrict__ bih, const float* __restrict__ bhh,
    const float* __restrict__ Wihn)
{
    extern __shared__ __align__(16) char sm[];
    uint32_t* sAhi = (uint32_t*)sm;                  // f16(Whh) image, 128KB
    float*    sCx  = (float*)(sm + 131072);          // partner partials, 48KB
    uint16_t* sB16 = (uint16_t*)(sm + 180224);       // hf0: f16(h), hf1: bf16(h)
    float*    sh   = (float*)(sm + 192512);          // double-buffered h
    float2*   sWnT = (float2*)(sm + 217088);

    const int tid = threadIdx.x, w = tid >> 5, l = tid & 31;
    const int rb = w & 7;
    const int hk = w >> 3;
    const int seq0 = blockIdx.x * SPB;
    const int r1 = rb * 16 + (l >> 2), r2 = r1 + 8;

    for (int i = tid; i < 32768; i += 512) sAhi[i] = g_whhA[i];
    for (int i = tid; i < 3072; i += 512) ((uint32_t*)sB16)[i] = 0;
    sWnT[tid] = make_float2(Wihn[(tid & 7) * 128 + 2 * (tid >> 3)],
                            Wihn[(tid & 7) * 128 + 2 * (tid >> 3) + 1]);

    float b4[4][2];
    float cs[3][4];
    float C[4][3][4];
    if (hk == 0) {
        #pragma unroll
        for (int g = 0; g < 4; g++) {
            b4[g][0] = bih[g * 128 + r1] + bhh[g * 128 + r1];
            b4[g][1] = bih[g * 128 + r2] + bhh[g * 128 + r2];
        }
        #pragma unroll
        for (int nt = 0; nt < 3; nt++)
            #pragma unroll
            for (int q = 0; q < 4; q++) cs[nt][q] = 0.f;
        #pragma unroll
        for (int g = 0; g < 4; g++)
            #pragma unroll
            for (int nt = 0; nt < 3; nt++) {
                const int sq = seq0 + nt * 8 + 2 * (l & 3);
                float2 v  = *(const float2*)&g_xpre[((size_t)(g * 128 + r1)) * NSEQ + sq];
                float2 u2 = *(const float2*)&g_xpre[((size_t)(g * 128 + r2)) * NSEQ + sq];
                C[g][nt][0] = v.x; C[g][nt][1] = v.y; C[g][nt][2] = u2.x; C[g][nt][3] = u2.y;
            }
    }
    __syncthreads();

    for (int t = 0; t < T_; t++) {
        if (hk) {
            #pragma unroll
            for (int g = 0; g < 4; g++)
                #pragma unroll
                for (int nt = 0; nt < 3; nt++)
                    #pragma unroll
                    for (int q = 0; q < 4; q++) C[g][nt][q] = 0.f;
        }
        // ---- MMA over this warp's K half (2-term mixed) ----
        {
            const uint32_t* pb = (const uint32_t*)sB16;
            uint4 rlo[4];
            #pragma unroll
            for (int u = 0; u < 4; u++) {
                const int ut = hk * 16 + u;
                rlo[u] = *(const uint4*)&g_whhA[32768 + ((ut >> 2) * 32 + (ut & 3) * 8 + rb) * 128 + l * 4];
            }
            #pragma unroll
            for (int kl = 0; kl < 4; kl++) {
                const int kt = hk * 4 + kl;
                uint2 bh[3], bl[3];
                #pragma unroll
                for (int nt = 0; nt < 3; nt++) {
                    bh[nt] = *(const uint2*)&pb[((0 * 8 + kt) * 3 + nt) * 64 + l * 2];
                    bl[nt] = *(const uint2*)&pb[((1 * 8 + kt) * 3 + nt) * 64 + l * 2];
                }
                #pragma unroll
                for (int g = 0; g < 4; g++) {
                    const int ul = kl * 4 + g;
                    uint4 a4 = *(const uint4*)&sAhi[(kt * 32 + g * 8 + rb) * 128 + l * 4];
                    uint32_t Ahi[4] = {a4.x, a4.y, a4.z, a4.w};
                    uint4 alv = rlo[ul & 3];
                    if (ul < 12) {
                        const int un = hk * 16 + ul + 4;
                        rlo[ul & 3] = *(const uint4*)&g_whhA[32768 + ((un >> 2) * 32 + (un & 3) * 8 + rb) * 128 + l * 4];
                    }
                    uint32_t Alo[4] = {alv.x, alv.y, alv.z, alv.w};
                    #pragma unroll
                    for (int nt = 0; nt < 3; nt++) {
                        mma_f16 (C[g][nt], Ahi, bh[nt].x, bh[nt].y);
                        mma_bf16(C[g][nt], Alo, bl[nt].x, bl[nt].y);
                    }
                }
            }
        }
        if (hk) {
            #pragma unroll
            for (int nt = 0; nt < 3; nt++)
                #pragma unroll
                for (int g = 0; g < 4; g++)
                    *(float4*)&sCx[(((nt * 4 + g) * 8 + rb) * 32 + l) * 4] =
                        make_float4(C[g][nt][0], C[g][nt][1], C[g][nt][2], C[g][nt][3]);
        }
        __syncthreads();    // S1

        if (hk == 0) {
            #pragma unroll
            for (int nt = 0; nt < 3; nt++)
                #pragma unroll
                for (int g = 0; g < 4; g++) {
                    float4 v = *(const float4*)&sCx[(((nt * 4 + g) * 8 + rb) * 32 + l) * 4];
                    C[g][nt][0] += v.x; C[g][nt][1] += v.y; C[g][nt][2] += v.z; C[g][nt][3] += v.w;
                }
            #pragma unroll
            for (int nt = 0; nt < 3; nt++)
                #pragma unroll
                for (int q = 0; q < 4; q++) {
                    const int rsel = q >> 1;
                    const int row = rsel ? r2 : r1;
                    const int s = nt * 8 + 2 * (l & 3) + (q & 1);
                    float gi = C[0][nt][q] + b4[0][rsel];
                    float gf = C[1][nt][q] + b4[1][rsel];
                    float gg = C[2][nt][q] + b4[2][rsel];
                    float go = C[3][nt][q] + b4[3][rsel];
                    float cc = sigf(gf) * cs[nt][q] + sigf(gi) * tanhf_(gg);
                    cs[nt][q] = cc;
                    float h = sigf(go) * tanhf_(cc);
                    sh[(t & 1) * 3072 + s * 128 + row] = h;
                    __half    hb = __float2half_rn(h);
                    __nv_bfloat16 lb = __float2bfloat16_rn(h);
                    const int kt2 = row >> 4, kk = row & 15;
                    const int lane2 = (s & 7) * 4 + ((kk & 7) >> 1), reg = kk >> 3, hf2 = kk & 1;
                    sB16[(((0 * 8 + kt2) * 3 + nt) * 32 + lane2) * 4 + reg * 2 + hf2] =
                        *reinterpret_cast<uint16_t*>(&hb);
                    sB16[(((1 * 8 + kt2) * 3 + nt) * 32 + lane2) * 4 + reg * 2 + hf2] =
                        *reinterpret_cast<uint16_t*>(&lb);
                }
            if (t < T_ - 1) {
                #pragma unroll
                for (int g = 0; g < 4; g++)
                    #pragma unroll
                    for (int nt = 0; nt < 3; nt++) {
                        const int sq = seq0 + nt * 8 + 2 * (l & 3);
                        float2 v  = *(const float2*)&g_xpre[((size_t)(t + 1) * 512 + g * 128 + r1) * NSEQ + sq];
                        float2 u2 = *(const float2*)&g_xpre[((size_t)(t + 1) * 512 + g * 128 + r2) * NSEQ + sq];
                        C[g][nt][0] = v.x; C[g][nt][1] = v.y; C[g][nt][2] = u2.x; C[g][nt][3] = u2.y;
                    }
            }
        } else {
            const int at = tid - 256;
            if (t > 0 && at < 192) {
                const int s = at >> 3, r8 = at & 7;
                const float2* hv = (const float2*)&sh[((t - 1) & 1) * 3072 + s * 128];
                float acc = 0.f;
                #pragma unroll
                for (int jj = 0; jj < 64; jj++) {
                    float2 h2v = hv[jj], w2 = sWnT[jj * 8 + r8];
                    acc = fmaf(h2v.x, w2.x, fmaf(h2v.y, w2.y, acc));
                }
                g_xpj[((size_t)(seq0 + s) * T_ + (t - 1)) * 8 + r8] = acc;
            }
        }
        __syncthreads();    // S2
    }

    if (tid < 192) {        // note-projection for t = 127
        const int s = tid >> 3, r8 = tid & 7;
        const float2* hv = (const float2*)&sh[((T_ - 1) & 1) * 3072 + s * 128];
        float acc = 0.f;
        #pragma unroll
        for (int jj = 0; jj < 64; jj++) {
            float2 h2v = hv[jj], w2 = sWnT[jj * 8 + r8];
            acc = fmaf(h2v.x, w2.x, fmaf(h2v.y, w2.y, acc));
        }
        g_xpj[((size_t)(seq0 + s) * T_ + (T_ - 1)) * 8 + r8] = acc;
    }
}

// ---------------- stage 2: 128x32, software-pipelined note chain ----------------
__global__ __launch_bounds__(32) void stage2_kernel(
    const float* __restrict__ Whhn,
    const float* __restrict__ bihn, const float* __restrict__ bhhn,
    float* __restrict__ out)
{
    int g = blockIdx.x * 32 + threadIdx.x;
    int b = g >> 7, t = g & 127;
    float W[16];
    #pragma unroll
    for (int i = 0; i < 16; i++) W[i] = Whhn[i];
    float bs[8];
    #pragma unroll
    for (int i = 0; i < 8; i++) bs[i] = bihn[i] + bhhn[i];
    float h0 = 0.f, h1 = 0.f, c0 = 0.f, c1 = 0.f;
    const float4* xp = reinterpret_cast<const float4*>(g_xpj);
    float* op = out + ((size_t)b * T_ + t) * (NOTES_ * 2);

    size_t base = ((size_t)(b * NOTES_) * T_ + t) * 2;   // float4 index; +256 per note
    float4 xa = __ldg(&xp[base]), xb = __ldg(&xp[base + 1]);
    for (int note = 0; note < NOTES_; note++) {
        float4 na, nb;
        if (note < NOTES_ - 1) {                          // prefetch next note off the chain
            na = __ldg(&xp[base + (size_t)(note + 1) * 256]);
            nb = __ldg(&xp[base + (size_t)(note + 1) * 256 + 1]);
        }
        float gi0 = xa.x + bs[0] + W[0]  * h0 + W[1]  * h1;
        float gi1 = xa.y + bs[1] + W[2]  * h0 + W[3]  * h1;
        float gf0 = xa.z + bs[2] + W[4]  * h0 + W[5]  * h1;
        float gf1 = xa.w + bs[3] + W[6]  * h0 + W[7]  * h1;
        float gg0 = xb.x + bs[4] + W[8]  * h0 + W[9]  * h1;
        float gg1 = xb.y + bs[5] + W[10] * h0 + W[11] * h1;
        float go0 = xb.z + bs[6] + W[12] * h0 + W[13] * h1;
        float go1 = xb.w + bs[7] + W[14] * h0 + W[15] * h1;
        c0 = sigf(gf0) * c0 + sigf(gi0) * tanhf_(gg0);
        c1 = sigf(gf1) * c1 + sigf(gi1) * tanhf_(gg1);
        h0 = sigf(go0) * tanhf_(c0);
        h1 = sigf(go1) * tanhf_(c1);
        op[note * 2] = h0; op[note * 2 + 1] = h1;
        xa = na; xb = nb;
    }
}

// ---------------- launch ----------------
extern "C" void kernel_launch(void* const* d_in, const int* in_sizes, int n_in,
                              void* d_out, int out_size)
{
    const float* x     = (const float*)d_in[0];
    const float* Wih_t = (const float*)d_in[1];
    const float* Whh_t = (const float*)d_in[2];
    const float* bih_t = (const float*)d_in[3];
    const float* bhh_t = (const float*)d_in[4];
    const float* Wih_n = (const float*)d_in[5];
    const float* Whh_n = (const float*)d_in[6];
    const float* bih_n = (const float*)d_in[7];
    const float* bhh_n = (const float*)d_in[8];
    float* out = (float*)d_out;

    const int smx = (40960 + 5120) * 4;   // 184320
    const int sm1 = 221184;
    cudaFuncSetAttribute(xproj_kernel,  cudaFuncAttributeMaxDynamicSharedMemorySize, smx);
    cudaFuncSetAttribute(stage1_kernel, cudaFuncAttributeMaxDynamicSharedMemorySize, sm1);

    pack_kernel<<<(106496 + 255) / 256, 256>>>(Wih_t, Whh_t);
    xproj_kernel<<<39 * 32, 512, smx>>>(x);
    stage1_kernel<<<NBLK, 512, sm1>>>(bih_t, bhh_t, Wih_n);
    stage2_kernel<<<(B_ * T_) / 32, 32>>>(Whh_n, bih_n, bhh_n, out);
}

// round 16
// speedup vs baseline: 1.7985x; 1.3043x over previous
#include <cuda_runtime.h>
#include <cuda_bf16.h>
#include <cuda_fp16.h>
#include <cstdint>

#define B_     32
#define NOTES_ 78
#define T_     128
#define NSEQ   2496
#define SPB    24
#define NCONS  104      // consumer blocks
#define NPROD  44       // producer blocks
#define NTILE  (39 * T_)   // 4992 producer tiles (64 seqs x 1 t)

// ---------------- device scratch ----------------
__device__ uint32_t g_whhA[2 * 8 * 32 * 128];   // hf0: f16(W), hf1: bf16(W - f16(W))
__device__ uint32_t g_wxA [2 * 5 * 32 * 128];
__device__ float    g_xpre[(size_t)T_ * 512 * NSEQ];
__device__ float    g_xpj[(size_t)NSEQ * T_ * 8];
__device__ int      g_done[T_ + 1];             // per-t completion counters (39 tiles each)

// ---------------- helpers ----------------
__device__ __forceinline__ float sigf(float x)   { return __fdividef(1.f, 1.f + __expf(-x)); }
__device__ __forceinline__ float tanhf_(float x) { return 2.f * sigf(2.f * x) - 1.f; }
__device__ __forceinline__ uint32_t bf2(float a, float b) {
    __nv_bfloat162 t = __floats2bfloat162_rn(a, b);
    return *reinterpret_cast<uint32_t*>(&t);
}
__device__ __forceinline__ uint32_t h2(float a, float b) {
    __half2 t = __floats2half2_rn(a, b);
    return *reinterpret_cast<uint32_t*>(&t);
}
__device__ __forceinline__ uint32_t resbf2(float a, float b) {
    __half2 t = __floats2half2_rn(a, b);
    float ra = a - __half2float(__low2half(t));
    float rb = b - __half2float(__high2half(t));
    return bf2(ra, rb);
}
__device__ __forceinline__ void mma_bf16(float* c, const uint32_t* a, uint32_t b0, uint32_t b1) {
    asm volatile("mma.sync.aligned.m16n8k16.row.col.f32.bf16.bf16.f32 "
        "{%0,%1,%2,%3},{%4,%5,%6,%7},{%8,%9},{%0,%1,%2,%3};"
        : "+f"(c[0]), "+f"(c[1]), "+f"(c[2]), "+f"(c[3])
        : "r"(a[0]), "r"(a[1]), "r"(a[2]), "r"(a[3]), "r"(b0), "r"(b1));
}
__device__ __forceinline__ void mma_f16(float* c, const uint32_t* a, uint32_t b0, uint32_t b1) {
    asm volatile("mma.sync.aligned.m16n8k16.row.col.f32.f16.f16.f32 "
        "{%0,%1,%2,%3},{%4,%5,%6,%7},{%8,%9},{%0,%1,%2,%3};"
        : "+f"(c[0]), "+f"(c[1]), "+f"(c[2]), "+f"(c[3])
        : "r"(a[0]), "r"(a[1]), "r"(a[2]), "r"(a[3]), "r"(b0), "r"(b1));
}

// ---------------- pack ----------------
__global__ void pack_kernel(const float* __restrict__ Wih, const float* __restrict__ Whh) {
    int i = blockIdx.x * 256 + threadIdx.x;
    if (i <= T_) g_done[i] = 0;              // zero counters every call (graph replay safe)
    if (i < 65536) {                         // Whh: [hf][kt8][mt32][lane][q]
        int q = i & 3, lane = (i >> 2) & 31, hf = i >> 15;
        int row = ((i >> 7) & 31) * 16 + (lane >> 2) + (q & 1) * 8;
        int k   = ((i >> 12) & 7) * 16 + 2 * (lane & 3) + (q >> 1) * 8;
        float v0 = Whh[row * 128 + k], v1 = Whh[row * 128 + k + 1];
        g_whhA[i] = hf ? resbf2(v0, v1) : h2(v0, v1);
    } else if (i < 106496) {                 // Wih: [hf][kt5][mt][lane][q]
        int j = i - 65536;
        int q = j & 3, lane = (j >> 2) & 31;
        int r = j >> 12, kt = r % 5, hf = r / 5;
        int row = ((j >> 7) & 31) * 16 + (lane >> 2) + (q & 1) * 8;
        int k = kt * 16 + 2 * (lane & 3) + (q >> 1) * 8;
        float v0 = Wih[row * 80 + k], v1 = Wih[row * 80 + k + 1];
        g_wxA[j] = hf ? resbf2(v0, v1) : h2(v0, v1);
    }
}

// ---------------- fused stage 1: consumers (blocks 0..103) + xproj producers (104..147) ----------------
__global__ __launch_bounds__(512, 1) void stage1_kernel(
    const float* __restrict__ bih, const float* __restrict__ bhh,
    const float* __restrict__ Wihn, const float* __restrict__ x)
{
    extern __shared__ __align__(16) char sm[];
    const int tid = threadIdx.x, w = tid >> 5, l = tid & 31;

    // ================= producer path =================
    if (blockIdx.x >= NCONS) {
        uint32_t* sWx = (uint32_t*)sm;              // 163840 B
        uint32_t* sB  = (uint32_t*)(sm + 163840);   // 20480 B
        for (int i = tid; i < 40960; i += 512) sWx[i] = g_wxA[i];

        for (int u = (int)blockIdx.x - NCONS; u < NTILE; u += NPROD) {
            const int t = u / 39;
            const int sg0 = (u - t * 39) * 64;
            __syncthreads();                        // sWx ready / prev sB reads + stores done
            for (int r = 0; r < 3; r++) {
                int idx = tid + r * 512;
                if (idx < 1280) {
                    int s = idx / 20, qq = idx - s * 20, k0 = qq * 4;
                    float4 v = *reinterpret_cast<const float4*>(&x[((size_t)(sg0 + s) * T_ + t) * 80 + k0]);
                    int kt = k0 >> 4, kk = k0 & 15, nt = s >> 3;
                    int lb = (s & 7) * 4 + ((kk & 7) >> 1), reg = kk >> 3;
                    uint32_t* ph = &sB[((0 * 5 + kt) * 8 + nt) * 64 + lb * 2 + reg];
                    uint32_t* pl = &sB[((1 * 5 + kt) * 8 + nt) * 64 + lb * 2 + reg];
                    ph[0] = h2(v.x, v.y);  ph[2] = h2(v.z, v.w);
                    pl[0] = bf2(v.x, v.y); pl[2] = bf2(v.z, v.w);
                }
            }
            __syncthreads();
            float C[2][8][4];
            #pragma unroll
            for (int a = 0; a < 2; a++)
                #pragma unroll
                for (int n = 0; n < 8; n++)
                    #pragma unroll
                    for (int q = 0; q < 4; q++) C[a][n][q] = 0.f;
            #pragma unroll
            for (int kt = 0; kt < 5; kt++) {
                uint32_t Ah[2][4], Al[2][4];
                #pragma unroll
                for (int mt = 0; mt < 2; mt++) {
                    const uint32_t* p  = &sWx[((0 * 5 + kt) * 32 + (2 * w + mt)) * 128 + l * 4];
                    const uint32_t* p2 = &sWx[((1 * 5 + kt) * 32 + (2 * w + mt)) * 128 + l * 4];
                    #pragma unroll
                    for (int q = 0; q < 4; q++) { Ah[mt][q] = p[q]; Al[mt][q] = p2[q]; }
                }
                #pragma unroll
                for (int nt = 0; nt < 8; nt++) {
                    uint32_t bh0 = sB[((0 * 5 + kt) * 8 + nt) * 64 + l * 2];
                    uint32_t bh1 = sB[((0 * 5 + kt) * 8 + nt) * 64 + l * 2 + 1];
                    uint32_t bl0 = sB[((1 * 5 + kt) * 8 + nt) * 64 + l * 2];
                    uint32_t bl1 = sB[((1 * 5 + kt) * 8 + nt) * 64 + l * 2 + 1];
                    #pragma unroll
                    for (int mt = 0; mt < 2; mt++) {
                        mma_f16 (C[mt][nt], Ah[mt], bh0, bh1);
                        mma_bf16(C[mt][nt], Al[mt], bl0, bl1);
                    }
                }
            }
            #pragma unroll
            for (int mt = 0; mt < 2; mt++)
                #pragma unroll
                for (int nt = 0; nt < 8; nt++) {
                    int row = (2 * w + mt) * 16 + (l >> 2);
                    int sq  = sg0 + nt * 8 + 2 * (l & 3);
                    float* d = &g_xpre[((size_t)t * 512 + row) * NSEQ + sq];
                    *reinterpret_cast<float2*>(d) = make_float2(C[mt][nt][0], C[mt][nt][1]);
                    *reinterpret_cast<float2*>(d + (size_t)8 * NSEQ) = make_float2(C[mt][nt][2], C[mt][nt][3]);
                }
            __syncthreads();                        // all stores of this tile done
            if (tid == 0) { __threadfence(); atomicAdd(&g_done[t], 1); }
        }
        return;
    }

    // ================= consumer path =================
    uint32_t* sAhi = (uint32_t*)sm;                  // 128KB f16(Whh) image
    float*    sCx  = (float*)(sm + 131072);          // partner partials
    uint16_t* sB16 = (uint16_t*)(sm + 180224);       // hf0: f16(h), hf1: bf16(h)
    float*    sh   = (float*)(sm + 192512);
    float2*   sWnT = (float2*)(sm + 217088);

    const int rb = w & 7;
    const int hk = w >> 3;
    const int seq0 = blockIdx.x * SPB;
    const int r1 = rb * 16 + (l >> 2), r2 = r1 + 8;

    for (int i = tid; i < 32768; i += 512) sAhi[i] = g_whhA[i];
    for (int i = tid; i < 3072; i += 512) ((uint32_t*)sB16)[i] = 0;
    sWnT[tid] = make_float2(Wihn[(tid & 7) * 128 + 2 * (tid >> 3)],
                            Wihn[(tid & 7) * 128 + 2 * (tid >> 3) + 1]);

    float b4[4][2];
    float cs[3][4];
    float C[4][3][4];
    if (hk == 0) {
        #pragma unroll
        for (int g = 0; g < 4; g++) {
            b4[g][0] = bih[g * 128 + r1] + bhh[g * 128 + r1];
            b4[g][1] = bih[g * 128 + r2] + bhh[g * 128 + r2];
        }
        #pragma unroll
        for (int nt = 0; nt < 3; nt++)
            #pragma unroll
            for (int q = 0; q < 4; q++) cs[nt][q] = 0.f;
        // wait for xpre(0), then preload into C
        if (l == 0) { while (((volatile int*)g_done)[0] < 39) __nanosleep(128); }
        __syncwarp(); __threadfence();
        #pragma unroll
        for (int g = 0; g < 4; g++)
            #pragma unroll
            for (int nt = 0; nt < 3; nt++) {
                const int sq = seq0 + nt * 8 + 2 * (l & 3);
                float2 v  = *(const float2*)&g_xpre[((size_t)(g * 128 + r1)) * NSEQ + sq];
                float2 u2 = *(const float2*)&g_xpre[((size_t)(g * 128 + r2)) * NSEQ + sq];
                C[g][nt][0] = v.x; C[g][nt][1] = v.y; C[g][nt][2] = u2.x; C[g][nt][3] = u2.y;
            }
    }
    __syncthreads();

    for (int t = 0; t < T_; t++) {
        if (hk) {
            #pragma unroll
            for (int g = 0; g < 4; g++)
                #pragma unroll
                for (int nt = 0; nt < 3; nt++)
                    #pragma unroll
                    for (int q = 0; q < 4; q++) C[g][nt][q] = 0.f;
        }
        // ---- MMA over this warp's K half (2-term mixed) ----
        {
            const uint32_t* pb = (const uint32_t*)sB16;
            uint4 rlo[4];
            #pragma unroll
            for (int u = 0; u < 4; u++) {
                const int ut = hk * 16 + u;
                rlo[u] = *(const uint4*)&g_whhA[32768 + ((ut >> 2) * 32 + (ut & 3) * 8 + rb) * 128 + l * 4];
            }
            #pragma unroll
            for (int kl = 0; kl < 4; kl++) {
                const int kt = hk * 4 + kl;
                uint2 bh[3], bl[3];
                #pragma unroll
                for (int nt = 0; nt < 3; nt++) {
                    bh[nt] = *(const uint2*)&pb[((0 * 8 + kt) * 3 + nt) * 64 + l * 2];
                    bl[nt] = *(const uint2*)&pb[((1 * 8 + kt) * 3 + nt) * 64 + l * 2];
                }
                #pragma unroll
                for (int g = 0; g < 4; g++) {
                    const int ul = kl * 4 + g;
                    uint4 a4 = *(const uint4*)&sAhi[(kt * 32 + g * 8 + rb) * 128 + l * 4];
                    uint32_t Ahi[4] = {a4.x, a4.y, a4.z, a4.w};
                    uint4 alv = rlo[ul & 3];
                    if (ul < 12) {
                        const int un = hk * 16 + ul + 4;
                        rlo[ul & 3] = *(const uint4*)&g_whhA[32768 + ((un >> 2) * 32 + (un & 3) * 8 + rb) * 128 + l * 4];
                    }
                    uint32_t Alo[4] = {alv.x, alv.y, alv.z, alv.w};
                    #pragma unroll
                    for (int nt = 0; nt < 3; nt++) {
                        mma_f16 (C[g][nt], Ahi, bh[nt].x, bh[nt].y);
                        mma_bf16(C[g][nt], Alo, bl[nt].x, bl[nt].y);
                    }
                }
            }
        }
        if (hk) {
            #pragma unroll
            for (int nt = 0; nt < 3; nt++)
                #pragma unroll
                for (int g = 0; g < 4; g++)
                    *(float4*)&sCx[(((nt * 4 + g) * 8 + rb) * 32 + l) * 4] =
                        make_float4(C[g][nt][0], C[g][nt][1], C[g][nt][2], C[g][nt][3]);
        }
        __syncthreads();    // S1

        if (hk == 0) {
            #pragma unroll
            for (int nt = 0; nt < 3; nt++)
                #pragma unroll
                for (int g = 0; g < 4; g++) {
                    float4 v = *(const float4*)&sCx[(((nt * 4 + g) * 8 + rb) * 32 + l) * 4];
                    C[g][nt][0] += v.x; C[g][nt][1] += v.y; C[g][nt][2] += v.z; C[g][nt][3] += v.w;
                }
            #pragma unroll
            for (int nt = 0; nt < 3; nt++)
                #pragma unroll
                for (int q = 0; q < 4; q++) {
                    const int rsel = q >> 1;
                    const int row = rsel ? r2 : r1;
                    const int s = nt * 8 + 2 * (l & 3) + (q & 1);
                    float gi = C[0][nt][q] + b4[0][rsel];
                    float gf = C[1][nt][q] + b4[1][rsel];
                    float gg = C[2][nt][q] + b4[2][rsel];
                    float go = C[3][nt][q] + b4[3][rsel];
                    float cc = sigf(gf) * cs[nt][q] + sigf(gi) * tanhf_(gg);
                    cs[nt][q] = cc;
                    float h = sigf(go) * tanhf_(cc);
                    sh[(t & 1) * 3072 + s * 128 + row] = h;
                    __half        hb = __float2half_rn(h);
                    __nv_bfloat16 lb = __float2bfloat16_rn(h);
                    const int kt2 = row >> 4, kk = row & 15;
                    const int lane2 = (s & 7) * 4 + ((kk & 7) >> 1), reg = kk >> 3, hf2 = kk & 1;
                    sB16[(((0 * 8 + kt2) * 3 + nt) * 32 + lane2) * 4 + reg * 2 + hf2] =
                        *reinterpret_cast<uint16_t*>(&hb);
                    sB16[(((1 * 8 + kt2) * 3 + nt) * 32 + lane2) * 4 + reg * 2 + hf2] =
                        *reinterpret_cast<uint16_t*>(&lb);
                }
            if (t < T_ - 1) {
                // gate on producers having finished slice t+1, then prefetch into dead C regs
                if (l == 0) { while (((volatile int*)g_done)[t + 1] < 39) __nanosleep(128); }
                __syncwarp(); __threadfence();
                #pragma unroll
                for (int g = 0; g < 4; g++)
                    #pragma unroll
                    for (int nt = 0; nt < 3; nt++) {
                        const int sq = seq0 + nt * 8 + 2 * (l & 3);
                        float2 v  = *(const float2*)&g_xpre[((size_t)(t + 1) * 512 + g * 128 + r1) * NSEQ + sq];
                        float2 u2 = *(const float2*)&g_xpre[((size_t)(t + 1) * 512 + g * 128 + r2) * NSEQ + sq];
                        C[g][nt][0] = v.x; C[g][nt][1] = v.y; C[g][nt][2] = u2.x; C[g][nt][3] = u2.y;
                    }
            }
        } else {
            const int at = tid - 256;
            if (t > 0 && at < 192) {
                const int s = at >> 3, r8 = at & 7;
                const float2* hv = (const float2*)&sh[((t - 1) & 1) * 3072 + s * 128];
                float acc = 0.f;
                #pragma unroll
                for (int jj = 0; jj < 64; jj++) {
                    float2 h2v = hv[jj], w2 = sWnT[jj * 8 + r8];
                    acc = fmaf(h2v.x, w2.x, fmaf(h2v.y, w2.y, acc));
                }
                g_xpj[((size_t)(seq0 + s) * T_ + (t - 1)) * 8 + r8] = acc;
            }
        }
        __syncthreads();    // S2
    }

    if (tid < 192) {        // note-projection for t = 127
        const int s = tid >> 3, r8 = tid & 7;
        const float2* hv = (const float2*)&sh[((T_ - 1) & 1) * 3072 + s * 128];
        float acc = 0.f;
        #pragma unroll
        for (int jj = 0; jj < 64; jj++) {
            float2 h2v = hv[jj], w2 = sWnT[jj * 8 + r8];
            acc = fmaf(h2v.x, w2.x, fmaf(h2v.y, w2.y, acc));
        }
        g_xpj[((size_t)(seq0 + s) * T_ + (T_ - 1)) * 8 + r8] = acc;
    }
}

// ---------------- stage 2: 128x32, software-pipelined note chain ----------------
__global__ __launch_bounds__(32) void stage2_kernel(
    const float* __restrict__ Whhn,
    const float* __restrict__ bihn, const float* __restrict__ bhhn,
    float* __restrict__ out)
{
    int g = blockIdx.x * 32 + threadIdx.x;
    int b = g >> 7, t = g & 127;
    float W[16];
    #pragma unroll
    for (int i = 0; i < 16; i++) W[i] = Whhn[i];
    float bs[8];
    #pragma unroll
    for (int i = 0; i < 8; i++) bs[i] = bihn[i] + bhhn[i];
    float h0 = 0.f, h1 = 0.f, c0 = 0.f, c1 = 0.f;
    const float4* xp = reinterpret_cast<const float4*>(g_xpj);
    float* op = out + ((size_t)b * T_ + t) * (NOTES_ * 2);

    size_t base = ((size_t)(b * NOTES_) * T_ + t) * 2;
    float4 xa = __ldg(&xp[base]), xb = __ldg(&xp[base + 1]);
    for (int note = 0; note < NOTES_; note++) {
        float4 na, nb;
        if (note < NOTES_ - 1) {
            na = __ldg(&xp[base + (size_t)(note + 1) * 256]);
            nb = __ldg(&xp[base + (size_t)(note + 1) * 256 + 1]);
        }
        float gi0 = xa.x + bs[0] + W[0]  * h0 + W[1]  * h1;
        float gi1 = xa.y + bs[1] + W[2]  * h0 + W[3]  * h1;
        float gf0 = xa.z + bs[2] + W[4]  * h0 + W[5]  * h1;
        float gf1 = xa.w + bs[3] + W[6]  * h0 + W[7]  * h1;
        float gg0 = xb.x + bs[4] + W[8]  * h0 + W[9]  * h1;
        float gg1 = xb.y + bs[5] + W[10] * h0 + W[11] * h1;
        float go0 = xb.z + bs[6] + W[12] * h0 + W[13] * h1;
        float go1 = xb.w + bs[7] + W[14] * h0 + W[15] * h1;
        c0 = sigf(gf0) * c0 + sigf(gi0) * tanhf_(gg0);
        c1 = sigf(gf1) * c1 + sigf(gi1) * tanhf_(gg1);
        h0 = sigf(go0) * tanhf_(c0);
        h1 = sigf(go1) * tanhf_(c1);
        op[note * 2] = h0; op[note * 2 + 1] = h1;
        xa = na; xb = nb;
    }
}

// ---------------- launch ----------------
extern "C" void kernel_launch(void* const* d_in, const int* in_sizes, int n_in,
                              void* d_out, int out_size)
{
    const float* x     = (const float*)d_in[0];
    const float* Wih_t = (const float*)d_in[1];
    const float* Whh_t = (const float*)d_in[2];
    const float* bih_t = (const float*)d_in[3];
    const float* bhh_t = (const float*)d_in[4];
    const float* Wih_n = (const float*)d_in[5];
    const float* Whh_n = (const float*)d_in[6];
    const float* bih_n = (const float*)d_in[7];
    const float* bhh_n = (const float*)d_in[8];
    float* out = (float*)d_out;

    const int sm1 = 221184;
    cudaFuncSetAttribute(stage1_kernel, cudaFuncAttributeMaxDynamicSharedMemorySize, sm1);

    pack_kernel<<<(106496 + 255) / 256, 256>>>(Wih_t, Whh_t);
    stage1_kernel<<<NCONS + NPROD, 512, sm1>>>(bih_t, bhh_t, Wih_n, x);
    stage2_kernel<<<(B_ * T_) / 32, 32>>>(Whh_n, bih_n, bhh_n, out);
}